// round 9
// baseline (speedup 1.0000x reference)
#include <cuda_runtime.h>
#include <cstdint>

#define KSEL   100
#define ESTR   128
#define BMAX   256
#define CAP    2048
#define TPB    256
#define SEGCAP 128
#define QB     8
#define SEGQ   (TPB * QB)      // 2048 quads per filter CTA
#define T0     8.3f            // filter threshold; exact fallback covers any input

// Scratch (__device__ globals; zero-init at load; every counter is reset by
// its consumer each invocation -> graph replays are deterministic).
__device__ int                g_cnt[BMAX];
__device__ int                g_done[BMAX];
__device__ int                g_rows;
__device__ unsigned long long g_buf[BMAX * CAP];
__device__ float              g_exps[BMAX * ESTR];
__device__ int                g_inds[BMAX * KSEL];

// Order-preserving float->uint key: bigger float => bigger key.
__device__ __forceinline__ unsigned fkey(float f) {
    unsigned u = __float_as_uint(f);
    return u ^ (unsigned)(((int)u >> 31) | 0x80000000);
}
__device__ __forceinline__ float fkey_inv(unsigned kk) {
    unsigned u = (kk & 0x80000000u) ? (kk ^ 0x80000000u) : ~kk;
    return __uint_as_float(u);
}

// ---------------------------------------------------------------------------
// ONE kernel: filter -> (last CTA per row) select -> (last row) sample.
// Filter issues all QB=8 float4 loads upfront (MLP=8, one latency round).
// ---------------------------------------------------------------------------
__global__ __launch_bounds__(TPB)
void fused_kernel(const float* __restrict__ logits,
                  const float* __restrict__ sp,
                  float* __restrict__ out, int V, int B, int nseg) {
    const int b    = blockIdx.x;
    const int s    = blockIdx.y;
    const int tid  = threadIdx.x;
    const int lane = tid & 31;
    const int wid  = tid >> 5;

    const float*  row = logits + (size_t)b * V;
    const int     V4  = V >> 2;
    const float4* r4  = (const float4*)row;
    const int     s0  = s * SEGQ;

    __shared__ unsigned s_n, s_nc;
    __shared__ int s_base, s_flag;
    __shared__ int s_part[TPB / 32];
    __shared__ unsigned long long s_loc[SEGCAP];
    __shared__ unsigned long long s_cand[512];
    __shared__ float s_inv[BMAX];

    if (tid == 0) s_n = 0;
    __syncthreads();

    // ==== Phase F: filter my 2048-quad segment, 8 upfront loads ====
    {
        float4 v[QB]; int idx[QB]; bool ok[QB];
#pragma unroll
        for (int j = 0; j < QB; j++) {
            idx[j] = s0 + j * TPB + tid;
            ok[j]  = idx[j] < V4;
            if (ok[j]) v[j] = r4[idx[j]];
        }
#pragma unroll
        for (int j = 0; j < QB; j++) {
            if (ok[j]) {
                float m = fmaxf(fmaxf(v[j].x, v[j].y), fmaxf(v[j].z, v[j].w));
                if (m > T0) {                       // rare (~1% of quads)
                    const int base = idx[j] * 4;
                    float vv[4] = {v[j].x, v[j].y, v[j].z, v[j].w};
#pragma unroll
                    for (int q = 0; q < 4; q++) {
                        if (vv[q] > T0) {
                            unsigned p = atomicAdd(&s_n, 1u);
                            if (p < SEGCAP)
                                s_loc[p] =
                                    ((unsigned long long)fkey(vv[q]) << 32) |
                                    (unsigned)(0xFFFFFFFFu - (unsigned)(base + q));
                        }
                    }
                }
            }
        }
    }
    if (s == 0) {                                    // scalar tail
        for (int i = V4 * 4 + tid; i < V; i += TPB) {
            float x = row[i];
            if (x > T0) {
                unsigned p = atomicAdd(&s_n, 1u);
                if (p < SEGCAP)
                    s_loc[p] = ((unsigned long long)fkey(x) << 32) |
                               (unsigned)(0xFFFFFFFFu - (unsigned)i);
            }
        }
    }
    __syncthreads();

    if (tid == 0) {
        unsigned nsu = s_n;
        int add = (nsu > SEGCAP) ? 1000000 : (int)nsu;   // poison -> fallback
        s_base = atomicAdd(&g_cnt[b], add);
    }
    __syncthreads();
    {
        int ns = min((int)s_n, SEGCAP);
        unsigned long long* buf = g_buf + (size_t)b * CAP;
        for (int t = tid; t < ns; t += TPB) {
            int pos = s_base + t;
            if (pos < CAP) buf[pos] = s_loc[t];
        }
    }
    __threadfence();
    __syncthreads();
    if (tid == 0) {
        int old = atomicAdd(&g_done[b], 1);
        s_flag = (old == nseg - 1);
    }
    __syncthreads();
    if (!s_flag) return;

    // ==== Phase S: last CTA of row b performs selection ====
    __threadfence();
    if (tid == 0) g_done[b] = 0;            // reset for next replay
    const int n = g_cnt[b];

    if (n >= KSEL && n <= 512) {
        const unsigned long long* buf = g_buf + (size_t)b * CAP;
        for (int t = tid; t < 512; t += TPB)
            s_cand[t] = (t < n) ? buf[t] : 0ull;
        __syncthreads();
    } else {
        // exact fallback: bitwise binary search over the full row
        unsigned X = 0;
        for (int bit = 31; bit >= 0; --bit) {
            unsigned trial = X | (1u << bit);
            int local = 0;
            for (int i = tid; i < V; i += TPB)
                local += (fkey(row[i]) >= trial);
#pragma unroll
            for (int off = 16; off; off >>= 1)
                local += __shfl_down_sync(0xffffffffu, local, off);
            if (lane == 0) s_part[wid] = local;
            __syncthreads();
            int cnt = 0;
#pragma unroll
            for (int w = 0; w < TPB / 32; w++) cnt += s_part[w];
            __syncthreads();
            if (cnt >= KSEL) X = trial;
        }
        if (tid == 0) s_nc = 0;
        for (int t = tid; t < 512; t += TPB) s_cand[t] = 0ull;
        __syncthreads();
        for (int i = tid; i < V; i += TPB) {
            unsigned kk = fkey(row[i]);
            if (kk >= X) {
                unsigned p = atomicAdd(&s_nc, 1u);
                if (p < 512)
                    s_cand[p] = ((unsigned long long)kk << 32) |
                                (unsigned)(0xFFFFFFFFu - (unsigned)i);
            }
        }
        __syncthreads();
    }
    if (tid == 0) g_cnt[b] = 0;             // reset for next replay

    // bitonic sort 512 desc with 256 threads (pairs disjoint per step)
    for (int ksz = 2; ksz <= 512; ksz <<= 1) {
        for (int j = ksz >> 1; j > 0; j >>= 1) {
            for (int t = tid; t < 512; t += TPB) {
                int ixj = t ^ j;
                if (ixj > t) {
                    bool desc = ((t & ksz) == 0);
                    unsigned long long a = s_cand[t], bb = s_cand[ixj];
                    if (desc ? (a < bb) : (a > bb)) {
                        s_cand[t] = bb;
                        s_cand[ixj] = a;
                    }
                }
            }
            __syncthreads();
        }
    }

    // emit sorted top-100 indices + exp terms (zero-padded to ESTR)
    if (tid < ESTR) {
        float e = 0.f;
        if (tid < KSEL) {
            unsigned long long comp = s_cand[tid];
            float val = fkey_inv((unsigned)(comp >> 32));
            g_inds[b * KSEL + tid] =
                (int)(0xFFFFFFFFu - (unsigned)(comp & 0xFFFFFFFFu));
            float v0 = fkey_inv((unsigned)(s_cand[0] >> 32));
            int   k  = min(max((int)sp[b * 3 + 0], 1), KSEL);
            float T  = sp[b * 3 + 2];
            if (tid < k) e = expf(val / T - v0 / T);
        }
        g_exps[b * ESTR + tid] = e;
    }
    __threadfence();
    __syncthreads();
    if (tid == 0) {
        int old = atomicAdd(&g_rows, 1);
        s_flag = (old == B - 1);
    }
    __syncthreads();
    if (!s_flag) return;

    // ==== Phase P: final CTA samples all rows (warp per row) ====
    if (tid == 0) g_rows = 0;               // reset for next replay
    __threadfence();

    const int NW = TPB / 32;
    for (int r = wid; r < B; r += NW) {
        const float* e = g_exps + r * ESTR;
        float ssum = 0.f;
#pragma unroll
        for (int c = 0; c < 4; c++) ssum += e[c * 32 + lane];
#pragma unroll
        for (int off = 16; off; off >>= 1)
            ssum += __shfl_xor_sync(0xffffffffu, ssum, off);
        if (lane == 0) s_inv[r] = 1.0f / ssum;   // csum[r][0]
    }
    __syncthreads();

    // jnp.min(csum) over the whole matrix = min_b 1/S_b
    float mn = s_inv[0];
    for (int i = 1; i < B; i++) mn = fminf(mn, s_inv[i]);

    for (int r = wid; r < B; r += NW) {
        const float* e = g_exps + r * ESTR;
        int   k    = min(max((int)sp[r * 3 + 0], 1), KSEL);
        float topp = sp[r * 3 + 1];
        float eff  = fmaxf(mn, topp);

        float p[4];
        float carry = 0.f;
#pragma unroll
        for (int c = 0; c < 4; c++) {
            float x = e[c * 32 + lane];
#pragma unroll
            for (int off = 1; off < 32; off <<= 1) {
                float y = __shfl_up_sync(0xffffffffu, x, off);
                if (lane >= off) x += y;
            }
            float pv = x + carry;
            p[c] = pv;
            carry = __shfl_sync(0xffffffffu, pv, 31);
        }
        float S = carry;
        float invS = 1.0f / S;

        // survivors = prefix {i<k : csum_i <= eff}, at least 1
        int ns = 0;
#pragma unroll
        for (int c = 0; c < 4; c++) {
            int gi = c * 32 + lane;
            bool cond = (gi < k) && (p[c] * invS <= eff);
            ns += __popc(__ballot_sync(0xffffffffu, cond));
        }
        if (ns < 1) ns = 1;

        // S2 = prefix sum at index ns-1
        int j = ns - 1, cc = j >> 5, ll = j & 31;
        float t0 = __shfl_sync(0xffffffffu, p[0], ll);
        float t1 = __shfl_sync(0xffffffffu, p[1], ll);
        float t2 = __shfl_sync(0xffffffffu, p[2], ll);
        float t3 = __shfl_sync(0xffffffffu, p[3], ll);
        float S2 = (cc == 0) ? t0 : (cc == 1) ? t1 : (cc == 2) ? t2 : t3;

        // counts = #{i<ns : prefix_i/S2 < 0.5}
        float half = 0.5f * S2;
        int cnt = 0;
#pragma unroll
        for (int c = 0; c < 4; c++) {
            int gi = c * 32 + lane;
            bool cond = (gi < ns) && (p[c] < half);
            cnt += __popc(__ballot_sync(0xffffffffu, cond));
        }
        if (cnt > ns - 1) cnt = ns - 1;
        if (cnt < 0) cnt = 0;

        if (lane == 0) out[r] = (float)g_inds[r * KSEL + cnt];
    }
}

// ---------------------------------------------------------------------------
extern "C" void kernel_launch(void* const* d_in, const int* in_sizes, int n_in,
                              void* d_out, int out_size) {
    int li = 0, si = 1;
    if (n_in >= 2 && in_sizes[0] < in_sizes[1]) { li = 1; si = 0; }
    const float* logits = (const float*)d_in[li];
    const float* sp     = (const float*)d_in[si];
    int B = in_sizes[si] / 3;
    int V = in_sizes[li] / B;
    if (B > BMAX) B = BMAX;

    int V4   = V >> 2;
    int nseg = (V4 + SEGQ - 1) / SEGQ;      // 16 for V=128000
    dim3 grid(B, nseg);
    fused_kernel<<<grid, TPB>>>(logits, sp, (float*)d_out, V, B, nseg);
}

// round 11
// speedup vs baseline: 2.0856x; 2.0856x over previous
#include <cuda_runtime.h>
#include <cstdint>

#define KSEL   100
#define ESTR   128
#define BMAX   256
#define CAP    2048
#define TPBF   256
#define QB     10
#define SEGQ   (TPBF * QB)     // 2560 quads per filter CTA
#define SEGCAP 128
#define TPBS   256
#define T0     9.0f            // filter threshold; exact fallback covers any input

// Scratch (__device__ globals; zero-init at load; g_cnt reset by select each
// invocation -> graph replays deterministic; ranks are order-independent).
__device__ int                g_cnt[BMAX];
__device__ unsigned long long g_buf[BMAX * CAP];
__device__ float              g_exps[BMAX * ESTR];
__device__ int                g_inds[BMAX * KSEL];

// Order-preserving float->uint key: bigger float => bigger key.
__device__ __forceinline__ unsigned fkey(float f) {
    unsigned u = __float_as_uint(f);
    return u ^ (unsigned)(((int)u >> 31) | 0x80000000);
}
__device__ __forceinline__ float fkey_inv(unsigned kk) {
    unsigned u = (kk & 0x80000000u) ? (kk ^ 0x80000000u) : ~kk;
    return __uint_as_float(u);
}

// ---------------------------------------------------------------------------
// Kernel 1: threshold filter. QB=10 upfront float4 loads, immediately reduced
// to per-quad max (low reg pressure); quad RELOADED from L1 on rare hit.
// ---------------------------------------------------------------------------
__global__ __launch_bounds__(TPBF)
void filter_kernel(const float* __restrict__ logits, int V) {
    const int b   = blockIdx.x;
    const int s   = blockIdx.y;
    const int tid = threadIdx.x;
    const float*  row = logits + (size_t)b * V;
    const int     V4  = V >> 2;
    const float4* r4  = (const float4*)row;
    const int     s0  = s * SEGQ;

    __shared__ unsigned s_n;
    __shared__ int s_base;
    __shared__ unsigned long long s_loc[SEGCAP];
    if (tid == 0) s_n = 0;
    __syncthreads();

    float m[QB];
    int   id[QB];
    bool  ok[QB];
    {
        float4 v[QB];
#pragma unroll
        for (int j = 0; j < QB; j++) {
            id[j] = s0 + j * TPBF + tid;
            ok[j] = id[j] < V4;
            if (ok[j]) v[j] = r4[id[j]];
            else       v[j] = make_float4(-3e38f, -3e38f, -3e38f, -3e38f);
        }
#pragma unroll
        for (int j = 0; j < QB; j++)
            m[j] = fmaxf(fmaxf(v[j].x, v[j].y), fmaxf(v[j].z, v[j].w));
    }
#pragma unroll
    for (int j = 0; j < QB; j++) {
        if (m[j] > T0) {                        // rare (~0.5% of quads)
            float4 w = r4[id[j]];               // L1 hit
            const int base = id[j] * 4;
            float vv[4] = {w.x, w.y, w.z, w.w};
#pragma unroll
            for (int q = 0; q < 4; q++) {
                if (vv[q] > T0) {
                    unsigned p = atomicAdd(&s_n, 1u);
                    if (p < SEGCAP)
                        s_loc[p] = ((unsigned long long)fkey(vv[q]) << 32) |
                                   (unsigned)(0xFFFFFFFFu - (unsigned)(base + q));
                }
            }
        }
    }
    if (s == 0) {                               // scalar tail (V % 4)
        for (int i = V4 * 4 + tid; i < V; i += TPBF) {
            float x = row[i];
            if (x > T0) {
                unsigned p = atomicAdd(&s_n, 1u);
                if (p < SEGCAP)
                    s_loc[p] = ((unsigned long long)fkey(x) << 32) |
                               (unsigned)(0xFFFFFFFFu - (unsigned)i);
            }
        }
    }
    __syncthreads();

    if (tid == 0) {
        unsigned nsu = s_n;
        int add = (nsu > SEGCAP) ? 1000000 : (int)nsu;   // poison -> fallback
        s_base = atomicAdd(&g_cnt[b], add);
    }
    __syncthreads();
    int ns = min((int)s_n, SEGCAP);
    unsigned long long* buf = g_buf + (size_t)b * CAP;
    for (int t = tid; t < ns; t += TPBF) {
        int pos = s_base + t;
        if (pos < CAP) buf[pos] = s_loc[t];
    }
}

// ---------------------------------------------------------------------------
// Kernel 2: rank-by-counting selection (no sort, 3 barriers).
// rank(c) = #{candidates > c}; composites unique -> ranks are a permutation.
// ---------------------------------------------------------------------------
__global__ __launch_bounds__(TPBS)
void select_kernel(const float* __restrict__ sp, int V,
                   const float* __restrict__ logits) {
    const int b    = blockIdx.x;
    const int tid  = threadIdx.x;
    const int lane = tid & 31;
    const int wid  = tid >> 5;

    __shared__ unsigned long long s_cand[512];
    __shared__ unsigned long long s_top;
    __shared__ unsigned s_nc;
    __shared__ int s_part[TPBS / 32];

    const int n = g_cnt[b];
    __syncthreads();                    // all threads read n before reset
    if (tid == 0) g_cnt[b] = 0;         // reset for next replay

    const float* row = logits + (size_t)b * V;
    int nc;

    if (n >= KSEL && n <= 512) {
        const unsigned long long* buf = g_buf + (size_t)b * CAP;
        s_cand[tid]       = (tid < n)       ? buf[tid]       : 0ull;
        s_cand[tid + 256] = (tid + 256 < n) ? buf[tid + 256] : 0ull;
        nc = n;
        __syncthreads();
    } else {
        // exact fallback: bitwise binary search for the 100th key over the row
        unsigned X = 0;
        for (int bit = 31; bit >= 0; --bit) {
            unsigned trial = X | (1u << bit);
            int local = 0;
            for (int i = tid; i < V; i += TPBS)
                local += (fkey(row[i]) >= trial);
#pragma unroll
            for (int off = 16; off; off >>= 1)
                local += __shfl_down_sync(0xffffffffu, local, off);
            if (lane == 0) s_part[wid] = local;
            __syncthreads();
            int cnt = 0;
#pragma unroll
            for (int w = 0; w < TPBS / 32; w++) cnt += s_part[w];
            __syncthreads();
            if (cnt >= KSEL) X = trial;
        }
        if (tid == 0) s_nc = 0;
        s_cand[tid] = 0ull;
        s_cand[tid + 256] = 0ull;
        __syncthreads();
        for (int i = tid; i < V; i += TPBS) {
            unsigned kk = fkey(row[i]);
            if (kk >= X) {
                unsigned p = atomicAdd(&s_nc, 1u);
                if (p < 512)
                    s_cand[p] = ((unsigned long long)kk << 32) |
                                (unsigned)(0xFFFFFFFFu - (unsigned)i);
            }
        }
        __syncthreads();
        nc = min((int)s_nc, 512);
    }

    // ranks via broadcast loop (conflict-free: all lanes read same address)
    unsigned long long my0 = s_cand[tid];
    unsigned long long my1 = s_cand[tid + 256];
    int r0 = 0, r1 = 0;
    for (int j = 0; j < nc; j++) {
        unsigned long long cj = s_cand[j];
        r0 += (cj > my0);
        r1 += (cj > my1);
    }
    if (tid < nc       && r0 == 0) s_top = my0;
    if (tid + 256 < nc && r1 == 0) s_top = my1;
    if (tid < ESTR) g_exps[b * ESTR + tid] = 0.f;     // zero-pad exps
    __syncthreads();

    const float v0 = fkey_inv((unsigned)(s_top >> 32));
    const int   k  = min(max((int)sp[b * 3 + 0], 1), KSEL);
    const float T  = sp[b * 3 + 2];
    const float v0T = v0 / T;

    if (tid < nc && r0 < KSEL) {
        float val = fkey_inv((unsigned)(my0 >> 32));
        g_inds[b * KSEL + r0] = (int)(0xFFFFFFFFu - (unsigned)(my0 & 0xFFFFFFFFu));
        g_exps[b * ESTR + r0] = (r0 < k) ? expf(val / T - v0T) : 0.f;
    }
    if (tid + 256 < nc && r1 < KSEL) {
        float val = fkey_inv((unsigned)(my1 >> 32));
        g_inds[b * KSEL + r1] = (int)(0xFFFFFFFFu - (unsigned)(my1 & 0xFFFFFFFFu));
        g_exps[b * ESTR + r1] = (r1 < k) ? expf(val / T - v0T) : 0.f;
    }
}

// ---------------------------------------------------------------------------
// Kernel 3: warp-per-row sampling (warp scan + ballots).
// Row stride derived from blockDim so launch and body cannot disagree.
// ---------------------------------------------------------------------------
__global__ __launch_bounds__(1024)
void sample_kernel(const float* __restrict__ sp, int B,
                   float* __restrict__ out) {
    const int tid  = threadIdx.x;
    const int w    = tid >> 5;
    const int lane = tid & 31;
    const int NW   = blockDim.x >> 5;          // number of warps
    __shared__ float s_inv[1024];

    for (int r = w; r < B; r += NW) {
        const float* e = g_exps + r * ESTR;
        float s = 0.f;
#pragma unroll
        for (int c = 0; c < 4; c++) s += e[c * 32 + lane];
#pragma unroll
        for (int off = 16; off; off >>= 1)
            s += __shfl_xor_sync(0xffffffffu, s, off);
        if (lane == 0) s_inv[r] = 1.0f / s;   // csum[r][0]
    }
    __syncthreads();

    // jnp.min(csum) over the whole matrix = min_b 1/S_b
    float m = s_inv[0];
    for (int i = 1; i < B; i++) m = fminf(m, s_inv[i]);

    for (int r = w; r < B; r += NW) {
        const float* e = g_exps + r * ESTR;
        int   k    = min(max((int)sp[r * 3 + 0], 1), KSEL);
        float topp = sp[r * 3 + 1];
        float eff  = fmaxf(m, topp);

        float p[4];
        float carry = 0.f;
#pragma unroll
        for (int c = 0; c < 4; c++) {
            float x = e[c * 32 + lane];
#pragma unroll
            for (int off = 1; off < 32; off <<= 1) {
                float y = __shfl_up_sync(0xffffffffu, x, off);
                if (lane >= off) x += y;
            }
            float pv = x + carry;
            p[c] = pv;
            carry = __shfl_sync(0xffffffffu, pv, 31);
        }
        float S = carry;
        float invS = 1.0f / S;

        int ns = 0;
#pragma unroll
        for (int c = 0; c < 4; c++) {
            int gi = c * 32 + lane;
            bool cond = (gi < k) && (p[c] * invS <= eff);
            ns += __popc(__ballot_sync(0xffffffffu, cond));
        }
        if (ns < 1) ns = 1;

        int j = ns - 1, cc = j >> 5, ll = j & 31;
        float t0 = __shfl_sync(0xffffffffu, p[0], ll);
        float t1 = __shfl_sync(0xffffffffu, p[1], ll);
        float t2 = __shfl_sync(0xffffffffu, p[2], ll);
        float t3 = __shfl_sync(0xffffffffu, p[3], ll);
        float S2 = (cc == 0) ? t0 : (cc == 1) ? t1 : (cc == 2) ? t2 : t3;

        float half = 0.5f * S2;
        int cnt = 0;
#pragma unroll
        for (int c = 0; c < 4; c++) {
            int gi = c * 32 + lane;
            bool cond = (gi < ns) && (p[c] < half);
            cnt += __popc(__ballot_sync(0xffffffffu, cond));
        }
        if (cnt > ns - 1) cnt = ns - 1;
        if (cnt < 0) cnt = 0;

        if (lane == 0) out[r] = (float)g_inds[r * KSEL + cnt];
    }
}

// ---------------------------------------------------------------------------
extern "C" void kernel_launch(void* const* d_in, const int* in_sizes, int n_in,
                              void* d_out, int out_size) {
    int li = 0, si = 1;
    if (n_in >= 2 && in_sizes[0] < in_sizes[1]) { li = 1; si = 0; }
    const float* logits = (const float*)d_in[li];
    const float* sp     = (const float*)d_in[si];
    int B = in_sizes[si] / 3;
    int V = in_sizes[li] / B;
    if (B > BMAX) B = BMAX;

    int V4   = V >> 2;
    int nseg = (V4 + SEGQ - 1) / SEGQ;      // 13 for V=128000
    dim3 gf(B, nseg);
    filter_kernel<<<gf, TPBF>>>(logits, V);
    select_kernel<<<B, TPBS>>>(sp, V, logits);
    sample_kernel<<<1, 1024>>>(sp, B, (float*)d_out);
}